// round 3
// baseline (speedup 1.0000x reference)
#include <cuda_runtime.h>
#include <cstdint>

// Problem constants
#define BB   256            // batch
#define DD_  512            // state dim
#define TT   256            // timesteps
#define SS   32             // time-block size (anchors every SS steps)
#define NDD  (DD_ * DD_)    // 262144 elems per DxD matrix
#define NBD  (BB * DD_)     // 131072 elems per BxD matrix

// Scratch: powers K^1..K^32 (slot j-1), anchors a_0..a_7
static __device__ float g_P[32 * NDD];  // 32 MB
static __device__ float g_A[8 * NBD];   // 4 MB

static __device__ __forceinline__ float* Pp(int j) { return g_P + (size_t)(j - 1) * NDD; }

// ---------------- packed f32x2 helpers (Blackwell FFMA2) ----------------
static __device__ __forceinline__ unsigned long long pack_dup(float x) {
    unsigned int xi = __float_as_uint(x);
    unsigned long long r;
    asm("mov.b64 %0, {%1, %1};" : "=l"(r) : "r"(xi));
    return r;
}
static __device__ __forceinline__ void ffma2(unsigned long long& d,
                                             unsigned long long a,
                                             unsigned long long b) {
    asm("fma.rn.f32x2 %0, %1, %2, %0;" : "+l"(d) : "l"(a), "l"(b));
}

// ---------------- 64x64 tile fp32 GEMM, K = 512, row-major ----------------
// A: [M x 512] row-major (row stride 512), B: [512 x 512] row-major,
// C row stride = c_stride. Grid: x = N/64 tiles, y = M/64 tiles.
// 128 threads: thread tile = 4 rows x 8 cols (4x4 f32x2 accumulators).
static __device__ __forceinline__ void gemm_tile(const float* __restrict__ A,
                                                 const float* __restrict__ B,
                                                 float* __restrict__ C,
                                                 int c_stride) {
    const int tid = threadIdx.x;
    const int m0 = blockIdx.y * 64;
    const int n0 = blockIdx.x * 64;

    __shared__ float As[16][64];  // [k][m]
    __shared__ float Bs[16][64];  // [k][n]

    // A tile load map: thread covers 8 consecutive k of one m-row half
    const int a_m = tid >> 1;           // 0..63
    const int a_k = (tid & 1) * 8;      // 0 or 8
    // B tile load map: 2 float4 per thread
    const int b_r = tid >> 4;           // 0..7 (and +8)
    const int b_c = (tid & 15) * 4;     // 0..60

    const int ty4 = (tid >> 3) * 4;     // thread row base (0..60)
    const int tx8 = (tid & 7) * 8;      // thread col base (0..56)

    unsigned long long acc[4][4];
#pragma unroll
    for (int i = 0; i < 4; ++i)
#pragma unroll
        for (int j = 0; j < 4; ++j) acc[i][j] = 0ull;

    const float* Abase = A + (size_t)(m0 + a_m) * DD_ + a_k;
    const float* Bbase = B + n0 + b_c;

#pragma unroll 1
    for (int kt = 0; kt < DD_ / 16; ++kt) {
        const int k0 = kt * 16;
        // global -> regs
        float4 av0 = *(const float4*)(Abase + k0);
        float4 av1 = *(const float4*)(Abase + k0 + 4);
        float4 bv0 = *(const float4*)(Bbase + (size_t)(k0 + b_r) * DD_);
        float4 bv1 = *(const float4*)(Bbase + (size_t)(k0 + b_r + 8) * DD_);
        __syncthreads();
        // regs -> smem (A transposed to [k][m])
        As[a_k + 0][a_m] = av0.x; As[a_k + 1][a_m] = av0.y;
        As[a_k + 2][a_m] = av0.z; As[a_k + 3][a_m] = av0.w;
        As[a_k + 4][a_m] = av1.x; As[a_k + 5][a_m] = av1.y;
        As[a_k + 6][a_m] = av1.z; As[a_k + 7][a_m] = av1.w;
        *(float4*)&Bs[b_r][b_c]     = bv0;
        *(float4*)&Bs[b_r + 8][b_c] = bv1;
        __syncthreads();

#pragma unroll
        for (int kk = 0; kk < 16; ++kk) {
            float4 a = *(const float4*)&As[kk][ty4];
            ulonglong2 b01 = *(const ulonglong2*)&Bs[kk][tx8];
            ulonglong2 b23 = *(const ulonglong2*)&Bs[kk][tx8 + 4];
            unsigned long long ar0 = pack_dup(a.x);
            unsigned long long ar1 = pack_dup(a.y);
            unsigned long long ar2 = pack_dup(a.z);
            unsigned long long ar3 = pack_dup(a.w);
            ffma2(acc[0][0], ar0, b01.x); ffma2(acc[0][1], ar0, b01.y);
            ffma2(acc[0][2], ar0, b23.x); ffma2(acc[0][3], ar0, b23.y);
            ffma2(acc[1][0], ar1, b01.x); ffma2(acc[1][1], ar1, b01.y);
            ffma2(acc[1][2], ar1, b23.x); ffma2(acc[1][3], ar1, b23.y);
            ffma2(acc[2][0], ar2, b01.x); ffma2(acc[2][1], ar2, b01.y);
            ffma2(acc[2][2], ar2, b23.x); ffma2(acc[2][3], ar2, b23.y);
            ffma2(acc[3][0], ar3, b01.x); ffma2(acc[3][1], ar3, b01.y);
            ffma2(acc[3][2], ar3, b23.x); ffma2(acc[3][3], ar3, b23.y);
        }
    }

    // epilogue
#pragma unroll
    for (int i = 0; i < 4; ++i) {
        float2 f0 = *(float2*)&acc[i][0];
        float2 f1 = *(float2*)&acc[i][1];
        float2 f2 = *(float2*)&acc[i][2];
        float2 f3 = *(float2*)&acc[i][3];
        float* crow = C + (size_t)(m0 + ty4 + i) * c_stride + n0 + tx8;
        *(float4*)(crow)     = make_float4(f0.x, f0.y, f1.x, f1.y);
        *(float4*)(crow + 4) = make_float4(f2.x, f2.y, f3.x, f3.y);
    }
}

// ---------------- kernels ----------------

// Copy K -> P[1], z0 -> a_0
__global__ void __launch_bounds__(512) k_copy(const float* __restrict__ K,
                                              const float* __restrict__ z0) {
    int i = blockIdx.x * blockDim.x + threadIdx.x;
    if (i < NDD) g_P[i] = K[i];
    else         g_A[i - NDD] = z0[i - NDD];
}

// Power doubling round: for z in [0, base): P[base+z+1] = P[base] @ P[z+1]
__global__ void __launch_bounds__(128) k_power(int base) {
    int z = blockIdx.z;
    gemm_tile(Pp(base), Pp(z + 1), Pp(base + z + 1), DD_);
}

// Anchor chain step: a_{i+1} = a_i @ K^32
__global__ void __launch_bounds__(128) k_anchor(int i) {
    gemm_tile(g_A + (size_t)i * NBD, Pp(SS), g_A + (size_t)(i + 1) * NBD, DD_);
}

// Fine phase: out[:, t, :] = a_{t/32} @ K^{(t%32)+1}, all t parallel (grid.z)
__global__ void __launch_bounds__(128) k_fine(float* __restrict__ out) {
    int t = blockIdx.z;
    const float* A = g_A + (size_t)(t >> 5) * NBD;
    const float* Bm = Pp((t & 31) + 1);
    float* C = out + (size_t)t * DD_;   // row stride = T*D = 131072
    gemm_tile(A, Bm, C, TT * DD_);
}

// ---------------- launch ----------------
extern "C" void kernel_launch(void* const* d_in, const int* in_sizes, int n_in,
                              void* d_out, int out_size) {
    const float* z0 = (const float*)d_in[0];
    const float* K  = (const float*)d_in[1];
    float* out = (float*)d_out;

    // 1) seed P[1]=K, a_0=z0
    k_copy<<<(NDD + NBD) / 512, 512>>>(K, z0);

    // 2) powers K^2..K^32 (5 doubling rounds)
    for (int base = 1; base <= 16; base *= 2)
        k_power<<<dim3(DD_ / 64, DD_ / 64, base), 128>>>(base);

    // 3) anchors a_1..a_7 (7 sequential steps with K^32)
    for (int i = 0; i < TT / SS - 1; ++i)
        k_anchor<<<dim3(DD_ / 64, BB / 64), 128>>>(i);

    // 4) all 256 output slices in one launch
    k_fine<<<dim3(DD_ / 64, BB / 64, TT), 128>>>(out);
}

// round 8
// speedup vs baseline: 2.8166x; 2.8166x over previous
#include <cuda_runtime.h>
#include <cuda_bf16.h>
#include <cstdint>

// ---------------- problem constants ----------------
#define BB   256
#define DD_  512
#define TT   256
#define NDD  (DD_ * DD_)     // 262144
#define NBD  (BB * DD_)      // 131072

// GEMM tile
#define TM   128
#define TN   128
#define KC   32              // k per stage
#define NSTG (DD_ / KC)      // 16 stages
#define THREADS 256

#define ROWH 40              // halves per smem row (32 data + 8 pad), 80 bytes
#define ROWB (ROWH * 2)      // 80
#define MATB (128 * ROWB)    // 10240 bytes per bf16 [128][32] matrix
#define BUFB (4 * MATB)      // Ah, Al, Bh, Bl per stage = 40960
#define SMEM_TOTAL (2 * BUFB)  // double buffered = 81920

// Scratch: powers K^1..K^32 (slots 1..32), K^64 (33), K^128 (34), transposed copies, anchors
static __device__ float g_P [34 * NDD];
static __device__ float g_PT[34 * NDD];
static __device__ float g_A [8 * NBD];

static __device__ __forceinline__ float* Pp (int j) { return g_P  + (size_t)(j - 1) * NDD; }
static __device__ __forceinline__ float* PTp(int j) { return g_PT + (size_t)(j - 1) * NDD; }

// ---------------- helpers ----------------
static __device__ __forceinline__ uint32_t smem_u32(const void* p) {
    uint32_t a;
    asm("{ .reg .u64 t; cvta.to.shared.u64 t, %1; cvt.u32.u64 %0, t; }" : "=r"(a) : "l"(p));
    return a;
}

// pack (x0, x1) -> bf16x2 with x0 in the LOW half. bf16 has fp32 exponent range:
// no overflow, no scaling needed, NaN-free for finite inputs.
static __device__ __forceinline__ uint32_t bf16x2_pack(float x0, float x1) {
    uint32_t d;
    asm("cvt.rn.bf16x2.f32 %0, %2, %1;" : "=r"(d) : "f"(x0), "f"(x1));
    return d;
}
// exact float value of the lo / hi bf16 halves (pure bit ops)
static __device__ __forceinline__ float bf16_lo_f(uint32_t u) {
    return __uint_as_float(u << 16);
}
static __device__ __forceinline__ float bf16_hi_f(uint32_t u) {
    return __uint_as_float(u & 0xFFFF0000u);
}

#define LDSM4(r0, r1, r2, r3, addr) \
    asm volatile("ldmatrix.sync.aligned.m8n8.x4.shared.b16 {%0,%1,%2,%3}, [%4];" \
                 : "=r"(r0), "=r"(r1), "=r"(r2), "=r"(r3) : "r"(addr))

#define MMA16816(c, a, b0, b1) \
    asm volatile("mma.sync.aligned.m16n8k16.row.col.f32.bf16.bf16.f32 " \
                 "{%0,%1,%2,%3}, {%4,%5,%6,%7}, {%8,%9}, {%0,%1,%2,%3};" \
                 : "+f"((c)[0]), "+f"((c)[1]), "+f"((c)[2]), "+f"((c)[3]) \
                 : "r"((a)[0]), "r"((a)[1]), "r"((a)[2]), "r"((a)[3]), \
                   "r"(b0), "r"(b1))

// split 16 floats (4x float4) into hi/lo bf16 pairs (8 uint32 each)
static __device__ __forceinline__ void split16(const float4* v, uint32_t* hi, uint32_t* lo) {
#pragma unroll
    for (int i = 0; i < 4; ++i) {
        uint32_t h0 = bf16x2_pack(v[i].x, v[i].y);
        uint32_t h1 = bf16x2_pack(v[i].z, v[i].w);
        hi[i * 2 + 0] = h0;
        hi[i * 2 + 1] = h1;
        lo[i * 2 + 0] = bf16x2_pack(v[i].x - bf16_lo_f(h0), v[i].y - bf16_hi_f(h0));
        lo[i * 2 + 1] = bf16x2_pack(v[i].z - bf16_lo_f(h1), v[i].w - bf16_hi_f(h1));
    }
}

// ---------------- 128x128x512 split-bf16 HMMA GEMM tile ----------------
// C[m][n] = sum_k A[m][k] * Bt[n][k]  (C = A @ Bt^T), C row-major stride cs.
// If Ct != nullptr also writes transposed copy Ct[n][m] (stride 512).
static __device__ void gemmt(const float* __restrict__ A, const float* __restrict__ Bt,
                             float* __restrict__ C, float* __restrict__ Ct,
                             size_t cs, int m0, int n0) {
    extern __shared__ char smem[];
    const uint32_t sb = smem_u32(smem);
    const int tid = threadIdx.x;
    const int wid = tid >> 5, l = tid & 31;
    const int wm = (wid >> 1) * 32;   // warp m offset in tile (0,32,64,96)
    const int wn = (wid & 1) * 64;    // warp n offset in tile (0 or 64)
    const int r = tid >> 1, h = tid & 1;   // writer: row 0..127, 16-half column half

    const float* ap = A  + (size_t)(m0 + r) * DD_ + h * 16;
    const float* bp = Bt + (size_t)(n0 + r) * DD_ + h * 16;

    float c[2][8][4];
#pragma unroll
    for (int i = 0; i < 2; ++i)
#pragma unroll
        for (int j = 0; j < 8; ++j)
#pragma unroll
            for (int q = 0; q < 4; ++q) c[i][j][q] = 0.0f;

    // writer smem byte offsets within one matrix (padded rows, no swizzle)
    const uint32_t wo0 = (uint32_t)(r * ROWB + h * 32);
    const uint32_t wo1 = wo0 + 16;

    // ldmatrix lane maps (x4: lanes 0-7/8-15/16-23/24-31 give matrices 0..3)
    const uint32_t a_row = (uint32_t)(wm + (l & 15));  // + mf*16
    const uint32_t a_ch  = (uint32_t)(l >> 4);         // + 2*kk
    const uint32_t b_row = (uint32_t)(wn + (l & 7) + ((l & 16) >> 1));  // + q*16
    const uint32_t b_ch  = (uint32_t)((l >> 3) & 1);   // + 2*kk

    float4 av[4], bv[4];
#pragma unroll
    for (int i = 0; i < 4; ++i) {
        av[i] = *(const float4*)(ap + i * 4);
        bv[i] = *(const float4*)(bp + i * 4);
    }

    for (int s = 0; s < NSTG; ++s) {
        const int b = s & 1;
        char* buf = smem + (size_t)b * BUFB;

        // convert current stage regs -> smem (hi/lo), then prefetch next stage
        {
            uint32_t hi[8], lo[8];
            split16(av, hi, lo);
            *(uint4*)(buf + wo0)        = make_uint4(hi[0], hi[1], hi[2], hi[3]);
            *(uint4*)(buf + wo1)        = make_uint4(hi[4], hi[5], hi[6], hi[7]);
            *(uint4*)(buf + MATB + wo0) = make_uint4(lo[0], lo[1], lo[2], lo[3]);
            *(uint4*)(buf + MATB + wo1) = make_uint4(lo[4], lo[5], lo[6], lo[7]);
            split16(bv, hi, lo);
            *(uint4*)(buf + 2 * MATB + wo0) = make_uint4(hi[0], hi[1], hi[2], hi[3]);
            *(uint4*)(buf + 2 * MATB + wo1) = make_uint4(hi[4], hi[5], hi[6], hi[7]);
            *(uint4*)(buf + 3 * MATB + wo0) = make_uint4(lo[0], lo[1], lo[2], lo[3]);
            *(uint4*)(buf + 3 * MATB + wo1) = make_uint4(lo[4], lo[5], lo[6], lo[7]);
        }
        if (s + 1 < NSTG) {
            const float* a2 = ap + (s + 1) * KC;
            const float* b2 = bp + (s + 1) * KC;
#pragma unroll
            for (int i = 0; i < 4; ++i) {
                av[i] = *(const float4*)(a2 + i * 4);
                bv[i] = *(const float4*)(b2 + i * 4);
            }
        }
        __syncthreads();

        const uint32_t sA  = sb + (uint32_t)b * BUFB;
        const uint32_t sAl = sA + MATB;
        const uint32_t sB  = sA + 2 * MATB;
        const uint32_t sBl = sA + 3 * MATB;

#pragma unroll
        for (int kk = 0; kk < 2; ++kk) {
            uint32_t ah[2][4], al[2][4], bh[4][4], bl[4][4];
            const uint32_t ach = (uint32_t)(2 * kk) + a_ch;
            const uint32_t bch = (uint32_t)(2 * kk) + b_ch;
#pragma unroll
            for (int mf = 0; mf < 2; ++mf) {
                const uint32_t off = (a_row + mf * 16) * ROWB + ach * 16;
                LDSM4(ah[mf][0], ah[mf][1], ah[mf][2], ah[mf][3], sA + off);
                LDSM4(al[mf][0], al[mf][1], al[mf][2], al[mf][3], sAl + off);
            }
#pragma unroll
            for (int q = 0; q < 4; ++q) {
                const uint32_t off = (b_row + q * 16) * ROWB + bch * 16;
                LDSM4(bh[q][0], bh[q][1], bh[q][2], bh[q][3], sB + off);
                LDSM4(bl[q][0], bl[q][1], bl[q][2], bl[q][3], sBl + off);
            }
#pragma unroll
            for (int mf = 0; mf < 2; ++mf)
#pragma unroll
                for (int nf = 0; nf < 8; ++nf) {
                    const int q = nf >> 1, hh = (nf & 1) * 2;
                    MMA16816(c[mf][nf], ah[mf], bh[q][hh], bh[q][hh + 1]);
                    MMA16816(c[mf][nf], ah[mf], bl[q][hh], bl[q][hh + 1]);
                    MMA16816(c[mf][nf], al[mf], bh[q][hh], bh[q][hh + 1]);
                }
        }
        __syncthreads();
    }

    // epilogue
    const int row0 = m0 + wm + (l >> 2);
    const int col0 = n0 + wn + 2 * (l & 3);
#pragma unroll
    for (int mf = 0; mf < 2; ++mf)
#pragma unroll
        for (int nf = 0; nf < 8; ++nf) {
            const int rr = row0 + mf * 16;
            const int cc = col0 + nf * 8;
            const float v0 = c[mf][nf][0];
            const float v1 = c[mf][nf][1];
            const float v2 = c[mf][nf][2];
            const float v3 = c[mf][nf][3];
            *(float2*)(C + (size_t)rr * cs + cc)       = make_float2(v0, v1);
            *(float2*)(C + (size_t)(rr + 8) * cs + cc) = make_float2(v2, v3);
            if (Ct) {
                Ct[(size_t)cc * DD_ + rr]           = v0;
                Ct[(size_t)(cc + 1) * DD_ + rr]     = v1;
                Ct[(size_t)cc * DD_ + rr + 8]       = v2;
                Ct[(size_t)(cc + 1) * DD_ + rr + 8] = v3;
            }
        }
}

// ---------------- kernels ----------------

// seed: P1 = K, P1T = K^T, a0 = z0
__global__ void __launch_bounds__(512) k_seed(const float* __restrict__ K,
                                              const float* __restrict__ z0) {
    int i = blockIdx.x * blockDim.x + threadIdx.x;
    if (i < NDD) {
        float v = K[i];
        g_P[i] = v;
        int r = i >> 9, cc = i & 511;
        g_PT[(size_t)cc * DD_ + r] = v;
    } else {
        g_A[i - NDD] = z0[i - NDD];
    }
}

// powers doubling: for z in [0,base): P_{base+z+1} = P_base @ P_{z+1}
__global__ void __launch_bounds__(THREADS) k_power(int base) {
    int z = blockIdx.z;
    gemmt(Pp(base), PTp(z + 1), Pp(base + z + 1), PTp(base + z + 1),
          DD_, blockIdx.y * TM, blockIdx.x * TN);
}

// round7: z0: K^64 = K^32 @ K^32;  z1: a1 = a0 @ K^32
__global__ void __launch_bounds__(THREADS) k_round7() {
    int m0 = blockIdx.y * TM, n0 = blockIdx.x * TN;
    if (blockIdx.z == 0) {
        gemmt(Pp(32), PTp(32), Pp(33), PTp(33), DD_, m0, n0);
    } else {
        if (m0 >= BB) return;
        gemmt(g_A, PTp(32), g_A + NBD, nullptr, DD_, m0, n0);
    }
}

// round8: z0: K^128 = K^64 @ K^64; z1: a2 = a0 @ K^64; z2: a3 = a1 @ K^64
__global__ void __launch_bounds__(THREADS) k_round8() {
    int m0 = blockIdx.y * TM, n0 = blockIdx.x * TN;
    if (blockIdx.z == 0) {
        gemmt(Pp(33), PTp(33), Pp(34), PTp(34), DD_, m0, n0);
    } else {
        if (m0 >= BB) return;
        int i = blockIdx.z - 1;  // 0 or 1
        gemmt(g_A + (size_t)i * NBD, PTp(33), g_A + (size_t)(i + 2) * NBD, nullptr,
              DD_, m0, n0);
    }
}

// round9: a_{4+z} = a_z @ K^128, z = 0..3
__global__ void __launch_bounds__(THREADS) k_round9() {
    int z = blockIdx.z;
    gemmt(g_A + (size_t)z * NBD, PTp(34), g_A + (size_t)(z + 4) * NBD, nullptr,
          DD_, blockIdx.y * TM, blockIdx.x * TN);
}

// fine: out[:, t, :] = a_{t>>5} @ K^{(t&31)+1}, all 256 t in parallel
__global__ void __launch_bounds__(THREADS) k_fine(float* __restrict__ out) {
    int t = blockIdx.z;
    const float* A  = g_A + (size_t)(t >> 5) * NBD;
    const float* Bt = PTp((t & 31) + 1);
    float* C = out + (size_t)t * DD_;          // row stride = T*D
    gemmt(A, Bt, C, nullptr, (size_t)TT * DD_, blockIdx.y * TM, blockIdx.x * TN);
}

// ---------------- launch ----------------
extern "C" void kernel_launch(void* const* d_in, const int* in_sizes, int n_in,
                              void* d_out, int out_size) {
    const float* z0 = (const float*)d_in[0];
    const float* K  = (const float*)d_in[1];
    float* out = (float*)d_out;

    cudaFuncSetAttribute(k_power,  cudaFuncAttributeMaxDynamicSharedMemorySize, SMEM_TOTAL);
    cudaFuncSetAttribute(k_round7, cudaFuncAttributeMaxDynamicSharedMemorySize, SMEM_TOTAL);
    cudaFuncSetAttribute(k_round8, cudaFuncAttributeMaxDynamicSharedMemorySize, SMEM_TOTAL);
    cudaFuncSetAttribute(k_round9, cudaFuncAttributeMaxDynamicSharedMemorySize, SMEM_TOTAL);
    cudaFuncSetAttribute(k_fine,   cudaFuncAttributeMaxDynamicSharedMemorySize, SMEM_TOTAL);

    k_seed<<<(NDD + NBD) / 512, 512>>>(K, z0);

    for (int base = 1; base <= 16; base *= 2)
        k_power<<<dim3(DD_ / TN, DD_ / TM, base), THREADS, SMEM_TOTAL>>>(base);

    k_round7<<<dim3(DD_ / TN, DD_ / TM, 2), THREADS, SMEM_TOTAL>>>();
    k_round8<<<dim3(DD_ / TN, DD_ / TM, 3), THREADS, SMEM_TOTAL>>>();
    k_round9<<<dim3(DD_ / TN, BB / TM, 4), THREADS, SMEM_TOTAL>>>();

    k_fine<<<dim3(DD_ / TN, BB / TM, TT), THREADS, SMEM_TOTAL>>>(out);
}

// round 9
// speedup vs baseline: 3.2134x; 1.1409x over previous
#include <cuda_runtime.h>
#include <cuda_bf16.h>
#include <cstdint>

// ---------------- problem constants ----------------
#define BB   256
#define DD_  512
#define TT   256
#define NDD  (DD_ * DD_)     // 262144
#define NBD  (BB * DD_)      // 131072

// GEMM tile
#define TM   128
#define TN   128
#define KC   32              // k per stage
#define NSTG (DD_ / KC)      // 16 stages
#define THREADS 256

#define ROWB 80              // smem row stride bytes (64 data + 16 pad)
#define MATB (128 * ROWB)    // 10240 bytes per bf16 [128][32] matrix
#define STGB (4 * MATB)      // Ah, Al, Bh, Bl per stage = 40960
#define NBUF 3
#define SMEM_TOTAL (NBUF * STGB)   // 122880

// ---------------- pre-split bf16 hi/lo global matrices ----------------
// powers K^1..K^32 slots 1..32, K^64 slot 33, K^128 slot 34 (row-major + transposed)
// anchors a_0..a_7 (row-major only; used only as A operand)
static __device__ __align__(16) uint16_t gPh [34 * NDD];
static __device__ __align__(16) uint16_t gPl [34 * NDD];
static __device__ __align__(16) uint16_t gPTh[34 * NDD];
static __device__ __align__(16) uint16_t gPTl[34 * NDD];
static __device__ __align__(16) uint16_t gAh [8 * NBD];
static __device__ __align__(16) uint16_t gAl [8 * NBD];

static __device__ __forceinline__ uint16_t* Ph (int j) { return gPh  + (size_t)(j - 1) * NDD; }
static __device__ __forceinline__ uint16_t* Pl (int j) { return gPl  + (size_t)(j - 1) * NDD; }
static __device__ __forceinline__ uint16_t* PTh(int j) { return gPTh + (size_t)(j - 1) * NDD; }
static __device__ __forceinline__ uint16_t* PTl(int j) { return gPTl + (size_t)(j - 1) * NDD; }

// ---------------- helpers ----------------
static __device__ __forceinline__ uint32_t smem_u32(const void* p) {
    uint32_t a;
    asm("{ .reg .u64 t; cvta.to.shared.u64 t, %1; cvt.u32.u64 %0, t; }" : "=r"(a) : "l"(p));
    return a;
}

// pack (x0, x1) -> bf16x2, x0 in LOW half
static __device__ __forceinline__ uint32_t bf16x2_pack(float x0, float x1) {
    uint32_t d;
    asm("cvt.rn.bf16x2.f32 %0, %2, %1;" : "=r"(d) : "f"(x0), "f"(x1));
    return d;
}
static __device__ __forceinline__ float bf16_lo_f(uint32_t u) { return __uint_as_float(u << 16); }
static __device__ __forceinline__ float bf16_hi_f(uint32_t u) { return __uint_as_float(u & 0xFFFF0000u); }

#define LDSM4(r0, r1, r2, r3, addr) \
    asm volatile("ldmatrix.sync.aligned.m8n8.x4.shared.b16 {%0,%1,%2,%3}, [%4];" \
                 : "=r"(r0), "=r"(r1), "=r"(r2), "=r"(r3) : "r"(addr))

#define MMA16816(c, a, b0, b1) \
    asm volatile("mma.sync.aligned.m16n8k16.row.col.f32.bf16.bf16.f32 " \
                 "{%0,%1,%2,%3}, {%4,%5,%6,%7}, {%8,%9}, {%0,%1,%2,%3};" \
                 : "+f"((c)[0]), "+f"((c)[1]), "+f"((c)[2]), "+f"((c)[3]) \
                 : "r"((a)[0]), "r"((a)[1]), "r"((a)[2]), "r"((a)[3]), \
                   "r"(b0), "r"(b1))

#define CP16(dst, src) \
    asm volatile("cp.async.cg.shared.global [%0], [%1], 16;" :: "r"(dst), "l"(src))
#define CPCOMMIT() asm volatile("cp.async.commit_group;" ::: "memory")
#define CPWAIT1()  asm volatile("cp.async.wait_group 1;"  ::: "memory")

// ---------------- 128x128x512 split-bf16 HMMA GEMM tile ----------------
// C[m][n] = sum_k (Ah+Al)[m][k] * (Bh+Bl)[n][k] with lo*lo dropped.
// Outputs (all nullable): fp32 C (stride cs); bf16 hi/lo row-major Ch/Cl
// (stride 512); bf16 hi/lo transposed CTh/CTl (stride 512).
static __device__ void gemmt(const uint16_t* __restrict__ Ah, const uint16_t* __restrict__ Al,
                             const uint16_t* __restrict__ Bh, const uint16_t* __restrict__ Bl,
                             float* __restrict__ C, size_t cs,
                             uint16_t* __restrict__ Ch, uint16_t* __restrict__ Cl,
                             uint16_t* __restrict__ CTh, uint16_t* __restrict__ CTl,
                             int m0, int n0) {
    extern __shared__ char smem[];
    const uint32_t sb = smem_u32(smem);
    const int tid = threadIdx.x;
    const int wid = tid >> 5, l = tid & 31;
    const int wm = (wid >> 1) * 32;   // warp m offset (0,32,64,96)
    const int wn = (wid & 1) * 64;    // warp n offset (0 or 64)

    // cp.async map: thread -> one 32B segment of one row of each matrix
    const int crow = tid >> 1;            // 0..127
    const int cseg = (tid & 1) * 16;      // halves offset within 32-half stage row
    const uint32_t wo = (uint32_t)(crow * ROWB + (tid & 1) * 32);
    const uint16_t* pa0 = Ah + (size_t)(m0 + crow) * DD_ + cseg;
    const uint16_t* pa1 = Al + (size_t)(m0 + crow) * DD_ + cseg;
    const uint16_t* pb0 = Bh + (size_t)(n0 + crow) * DD_ + cseg;
    const uint16_t* pb1 = Bl + (size_t)(n0 + crow) * DD_ + cseg;

    float c[2][8][4];
#pragma unroll
    for (int i = 0; i < 2; ++i)
#pragma unroll
        for (int j = 0; j < 8; ++j)
#pragma unroll
            for (int q = 0; q < 4; ++q) c[i][j][q] = 0.0f;

    // ldmatrix lane maps (x4)
    const uint32_t a_row = (uint32_t)(wm + (l & 15));                   // + mf*16
    const uint32_t a_ch  = (uint32_t)(l >> 4);                          // + 2*kk
    const uint32_t b_row = (uint32_t)(wn + (l & 7) + ((l & 16) >> 1));  // + q*16
    const uint32_t b_ch  = (uint32_t)((l >> 3) & 1);                    // + 2*kk

    auto issue = [&](int s) {
        const uint32_t d = sb + (uint32_t)(s % NBUF) * STGB + wo;
        const int ko = s * KC;
        CP16(d,                 pa0 + ko);
        CP16(d + 16,            pa0 + ko + 8);
        CP16(d + MATB,          pa1 + ko);
        CP16(d + MATB + 16,     pa1 + ko + 8);
        CP16(d + 2 * MATB,      pb0 + ko);
        CP16(d + 2 * MATB + 16, pb0 + ko + 8);
        CP16(d + 3 * MATB,      pb1 + ko);
        CP16(d + 3 * MATB + 16, pb1 + ko + 8);
    };

    issue(0); CPCOMMIT();
    issue(1); CPCOMMIT();

    for (int s = 0; s < NSTG; ++s) {
        CPWAIT1();            // stage s resident (<=1 newer group pending)
        __syncthreads();      // publish to all warps; also fences buffer reuse

        const uint32_t base = sb + (uint32_t)(s % NBUF) * STGB;
        const uint32_t sA  = base;
        const uint32_t sAl = base + MATB;
        const uint32_t sB  = base + 2 * MATB;
        const uint32_t sBl = base + 3 * MATB;

#pragma unroll
        for (int kk = 0; kk < 2; ++kk) {
            uint32_t ah[2][4], al[2][4], bh[4][4], bl[4][4];
            const uint32_t ach = (uint32_t)(2 * kk) + a_ch;
            const uint32_t bch = (uint32_t)(2 * kk) + b_ch;
#pragma unroll
            for (int mf = 0; mf < 2; ++mf) {
                const uint32_t off = (a_row + mf * 16) * ROWB + ach * 16;
                LDSM4(ah[mf][0], ah[mf][1], ah[mf][2], ah[mf][3], sA + off);
                LDSM4(al[mf][0], al[mf][1], al[mf][2], al[mf][3], sAl + off);
            }
#pragma unroll
            for (int q = 0; q < 4; ++q) {
                const uint32_t off = (b_row + q * 16) * ROWB + bch * 16;
                LDSM4(bh[q][0], bh[q][1], bh[q][2], bh[q][3], sB + off);
                LDSM4(bl[q][0], bl[q][1], bl[q][2], bl[q][3], sBl + off);
            }
#pragma unroll
            for (int mf = 0; mf < 2; ++mf)
#pragma unroll
                for (int nf = 0; nf < 8; ++nf) {
                    const int q = nf >> 1, hh = (nf & 1) * 2;
                    MMA16816(c[mf][nf], ah[mf], bh[q][hh], bh[q][hh + 1]);
                    MMA16816(c[mf][nf], ah[mf], bl[q][hh], bl[q][hh + 1]);
                    MMA16816(c[mf][nf], al[mf], bh[q][hh], bh[q][hh + 1]);
                }
        }
        if (s + 2 < NSTG) issue(s + 2);
        CPCOMMIT();           // empty group when nothing issued keeps counts aligned
    }

    // ---------------- epilogue ----------------
    const int row0 = m0 + wm + (l >> 2);
    const int col0 = n0 + wn + 2 * (l & 3);
#pragma unroll
    for (int mf = 0; mf < 2; ++mf)
#pragma unroll
        for (int nf = 0; nf < 8; ++nf) {
            const int rr = row0 + mf * 16;
            const int cc = col0 + nf * 8;
            const float v0 = c[mf][nf][0], v1 = c[mf][nf][1];
            const float v2 = c[mf][nf][2], v3 = c[mf][nf][3];
            if (C) {
                *(float2*)(C + (size_t)rr * cs + cc)       = make_float2(v0, v1);
                *(float2*)(C + (size_t)(rr + 8) * cs + cc) = make_float2(v2, v3);
            }
            if (Ch) {
                uint32_t p01 = bf16x2_pack(v0, v1);
                uint32_t p23 = bf16x2_pack(v2, v3);
                uint32_t q01 = bf16x2_pack(v0 - bf16_lo_f(p01), v1 - bf16_hi_f(p01));
                uint32_t q23 = bf16x2_pack(v2 - bf16_lo_f(p23), v3 - bf16_hi_f(p23));
                *(uint32_t*)(Ch + (size_t)rr * DD_ + cc)       = p01;
                *(uint32_t*)(Cl + (size_t)rr * DD_ + cc)       = q01;
                *(uint32_t*)(Ch + (size_t)(rr + 8) * DD_ + cc) = p23;
                *(uint32_t*)(Cl + (size_t)(rr + 8) * DD_ + cc) = q23;
                if (CTh) {
                    CTh[(size_t)cc * DD_ + rr]           = (uint16_t)p01;
                    CTh[(size_t)(cc + 1) * DD_ + rr]     = (uint16_t)(p01 >> 16);
                    CTh[(size_t)cc * DD_ + rr + 8]       = (uint16_t)p23;
                    CTh[(size_t)(cc + 1) * DD_ + rr + 8] = (uint16_t)(p23 >> 16);
                    CTl[(size_t)cc * DD_ + rr]           = (uint16_t)q01;
                    CTl[(size_t)(cc + 1) * DD_ + rr]     = (uint16_t)(q01 >> 16);
                    CTl[(size_t)cc * DD_ + rr + 8]       = (uint16_t)q23;
                    CTl[(size_t)(cc + 1) * DD_ + rr + 8] = (uint16_t)(q23 >> 16);
                }
            }
        }
}

// ---------------- kernels ----------------

// seed: split K -> slot1 (row-major + transposed), z0 -> anchor 0
__global__ void __launch_bounds__(512) k_seed(const float* __restrict__ K,
                                              const float* __restrict__ z0) {
    int i = blockIdx.x * blockDim.x + threadIdx.x;
    if (i < NDD) {
        float v = K[i];
        uint32_t p = bf16x2_pack(v, v);
        uint16_t hp = (uint16_t)p;
        uint16_t lp = (uint16_t)bf16x2_pack(v - bf16_lo_f(p), 0.0f);
        int r = i >> 9, cc = i & 511;
        gPh[i] = hp;  gPl[i] = lp;
        gPTh[(size_t)cc * DD_ + r] = hp;
        gPTl[(size_t)cc * DD_ + r] = lp;
    } else {
        int j = i - NDD;
        float v = z0[j];
        uint32_t p = bf16x2_pack(v, v);
        gAh[j] = (uint16_t)p;
        gAl[j] = (uint16_t)bf16x2_pack(v - bf16_lo_f(p), 0.0f);
    }
}

// powers doubling: for z in [0,base): P_{base+z+1} = P_base @ P_{z+1}
__global__ void __launch_bounds__(THREADS) k_power(int base) {
    int z = blockIdx.z;
    int dst = base + z + 1;
    gemmt(Ph(base), Pl(base), PTh(z + 1), PTl(z + 1),
          nullptr, 0, Ph(dst), Pl(dst), PTh(dst), PTl(dst),
          blockIdx.y * TM, blockIdx.x * TN);
}

// round7: z0: K^64 = K^32 @ K^32 (slot 33);  z1: a1 = a0 @ K^32
__global__ void __launch_bounds__(THREADS) k_round7() {
    int m0 = blockIdx.y * TM, n0 = blockIdx.x * TN;
    if (blockIdx.z == 0) {
        gemmt(Ph(32), Pl(32), PTh(32), PTl(32),
              nullptr, 0, Ph(33), Pl(33), PTh(33), PTl(33), m0, n0);
    } else {
        if (m0 >= BB) return;
        gemmt(gAh, gAl, PTh(32), PTl(32),
              nullptr, 0, gAh + NBD, gAl + NBD, nullptr, nullptr, m0, n0);
    }
}

// round8: z0: K^128 = K^64 @ K^64 (slot 34); z1: a2 = a0 @ K^64; z2: a3 = a1 @ K^64
__global__ void __launch_bounds__(THREADS) k_round8() {
    int m0 = blockIdx.y * TM, n0 = blockIdx.x * TN;
    if (blockIdx.z == 0) {
        gemmt(Ph(33), Pl(33), PTh(33), PTl(33),
              nullptr, 0, Ph(34), Pl(34), PTh(34), PTl(34), m0, n0);
    } else {
        if (m0 >= BB) return;
        int i = blockIdx.z - 1;  // 0 or 1
        gemmt(gAh + (size_t)i * NBD, gAl + (size_t)i * NBD, PTh(33), PTl(33),
              nullptr, 0, gAh + (size_t)(i + 2) * NBD, gAl + (size_t)(i + 2) * NBD,
              nullptr, nullptr, m0, n0);
    }
}

// round9: a_{4+z} = a_z @ K^128, z = 0..3
__global__ void __launch_bounds__(THREADS) k_round9() {
    int z = blockIdx.z;
    gemmt(gAh + (size_t)z * NBD, gAl + (size_t)z * NBD, PTh(34), PTl(34),
          nullptr, 0, gAh + (size_t)(z + 4) * NBD, gAl + (size_t)(z + 4) * NBD,
          nullptr, nullptr, blockIdx.y * TM, blockIdx.x * TN);
}

// fine: out[:, t, :] = a_{t>>5} @ K^{(t&31)+1}, all 256 t in parallel
__global__ void __launch_bounds__(THREADS) k_fine(float* __restrict__ out) {
    int t = blockIdx.z;
    gemmt(gAh + (size_t)(t >> 5) * NBD, gAl + (size_t)(t >> 5) * NBD,
          PTh((t & 31) + 1), PTl((t & 31) + 1),
          out + (size_t)t * DD_, (size_t)TT * DD_,
          nullptr, nullptr, nullptr, nullptr,
          blockIdx.y * TM, blockIdx.x * TN);
}

// ---------------- launch ----------------
extern "C" void kernel_launch(void* const* d_in, const int* in_sizes, int n_in,
                              void* d_out, int out_size) {
    const float* z0 = (const float*)d_in[0];
    const float* K  = (const float*)d_in[1];
    float* out = (float*)d_out;

    cudaFuncSetAttribute(k_power,  cudaFuncAttributeMaxDynamicSharedMemorySize, SMEM_TOTAL);
    cudaFuncSetAttribute(k_round7, cudaFuncAttributeMaxDynamicSharedMemorySize, SMEM_TOTAL);
    cudaFuncSetAttribute(k_round8, cudaFuncAttributeMaxDynamicSharedMemorySize, SMEM_TOTAL);
    cudaFuncSetAttribute(k_round9, cudaFuncAttributeMaxDynamicSharedMemorySize, SMEM_TOTAL);
    cudaFuncSetAttribute(k_fine,   cudaFuncAttributeMaxDynamicSharedMemorySize, SMEM_TOTAL);

    k_seed<<<(NDD + NBD) / 512, 512>>>(K, z0);

    for (int base = 1; base <= 16; base *= 2)
        k_power<<<dim3(DD_ / TN, DD_ / TM, base), THREADS, SMEM_TOTAL>>>(base);

    k_round7<<<dim3(DD_ / TN, DD_ / TM, 2), THREADS, SMEM_TOTAL>>>();
    k_round8<<<dim3(DD_ / TN, DD_ / TM, 3), THREADS, SMEM_TOTAL>>>();
    k_round9<<<dim3(DD_ / TN, BB / TM, 4), THREADS, SMEM_TOTAL>>>();

    k_fine<<<dim3(DD_ / TN, BB / TM, TT), THREADS, SMEM_TOTAL>>>(out);
}

// round 10
// speedup vs baseline: 5.2181x; 1.6239x over previous
#include <cuda_runtime.h>
#include <cuda_bf16.h>
#include <cstdint>

// ---------------- problem constants ----------------
#define BB   256
#define DD_  512
#define TT   256
#define NDD  (DD_ * DD_)     // 262144
#define NBD  (BB * DD_)      // 131072

#define KC   32              // k per stage
#define NSTG (DD_ / KC)      // 16 stages
#define THREADS 256
#define NBUF 3

// smem per stage for a TMv x TNv tile: (Ah + Al) TMv*64B + (Bh + Bl) TNv*64B
#define STG_BYTES(TMv, TNv) (2 * (TMv) * 64 + 2 * (TNv) * 64)
#define SMEM_BIG   (NBUF * STG_BYTES(128, 128))   // 98304
#define SMEM_SMALL (NBUF * STG_BYTES(64, 64))     // 49152

// ---------------- pre-split bf16 hi/lo global matrices ----------------
static __device__ __align__(16) uint16_t gPh [34 * NDD];
static __device__ __align__(16) uint16_t gPl [34 * NDD];
static __device__ __align__(16) uint16_t gPTh[34 * NDD];
static __device__ __align__(16) uint16_t gPTl[34 * NDD];
static __device__ __align__(16) uint16_t gAh [8 * NBD];
static __device__ __align__(16) uint16_t gAl [8 * NBD];

static __device__ __forceinline__ uint16_t* Ph (int j) { return gPh  + (size_t)(j - 1) * NDD; }
static __device__ __forceinline__ uint16_t* Pl (int j) { return gPl  + (size_t)(j - 1) * NDD; }
static __device__ __forceinline__ uint16_t* PTh(int j) { return gPTh + (size_t)(j - 1) * NDD; }
static __device__ __forceinline__ uint16_t* PTl(int j) { return gPTl + (size_t)(j - 1) * NDD; }

// ---------------- helpers ----------------
static __device__ __forceinline__ uint32_t smem_u32(const void* p) {
    uint32_t a;
    asm("{ .reg .u64 t; cvta.to.shared.u64 t, %1; cvt.u32.u64 %0, t; }" : "=r"(a) : "l"(p));
    return a;
}
static __device__ __forceinline__ uint32_t bf16x2_pack(float x0, float x1) {
    uint32_t d;
    asm("cvt.rn.bf16x2.f32 %0, %2, %1;" : "=r"(d) : "f"(x0), "f"(x1));
    return d;
}
static __device__ __forceinline__ float bf16_lo_f(uint32_t u) { return __uint_as_float(u << 16); }
static __device__ __forceinline__ float bf16_hi_f(uint32_t u) { return __uint_as_float(u & 0xFFFF0000u); }

// swizzle for 64B rows: XOR 16B-chunk bits [5:4] with row bits [2:1] (off bits [8:7]).
// Even rows live in banks 0-15, odd rows in banks 16-31; within each parity class the
// 4 rows of an 8-row ldmatrix group land on 4 distinct 16B chunks -> conflict-free.
static __device__ __forceinline__ uint32_t swz64(uint32_t off) {
    return off ^ ((off >> 3) & 0x30u);
}

#define LDSM4(r0, r1, r2, r3, addr) \
    asm volatile("ldmatrix.sync.aligned.m8n8.x4.shared.b16 {%0,%1,%2,%3}, [%4];" \
                 : "=r"(r0), "=r"(r1), "=r"(r2), "=r"(r3) : "r"(addr))

#define MMA16816(c, a, b0, b1) \
    asm volatile("mma.sync.aligned.m16n8k16.row.col.f32.bf16.bf16.f32 " \
                 "{%0,%1,%2,%3}, {%4,%5,%6,%7}, {%8,%9}, {%0,%1,%2,%3};" \
                 : "+f"((c)[0]), "+f"((c)[1]), "+f"((c)[2]), "+f"((c)[3]) \
                 : "r"((a)[0]), "r"((a)[1]), "r"((a)[2]), "r"((a)[3]), \
                   "r"(b0), "r"(b1))

#define CP16(dst, src) \
    asm volatile("cp.async.cg.shared.global [%0], [%1], 16;" :: "r"(dst), "l"(src))
#define CPCOMMIT() asm volatile("cp.async.commit_group;" ::: "memory")
#define CPWAIT1()  asm volatile("cp.async.wait_group 1;"  ::: "memory")

// ---------------- TMv x TNv x 512 split-bf16 HMMA GEMM tile ----------------
// C[m][n] = sum_k (Ah+Al)[m][k]*(Bh+Bl)[n][k], lo*lo dropped. Outputs nullable:
// fp32 C (stride cs); bf16 hi/lo row-major Ch/Cl (stride 512); transposed CTh/CTl.
template<int TMv, int TNv>
static __device__ void gemmt(const uint16_t* __restrict__ Ah, const uint16_t* __restrict__ Al,
                             const uint16_t* __restrict__ Bh, const uint16_t* __restrict__ Bl,
                             float* __restrict__ C, size_t cs,
                             uint16_t* __restrict__ Ch, uint16_t* __restrict__ Cl,
                             uint16_t* __restrict__ CTh, uint16_t* __restrict__ CTl,
                             int m0, int n0) {
    constexpr int NWM = TMv / 32;        // warps along m (each warp covers 32 rows)
    constexpr int NWN = 8 / NWM;         // warps along n
    constexpr int WN  = TNv / NWN;       // warp n extent (64 or 16)
    constexpr int NF  = WN / 8;          // n fragments per warp (8 or 2)
    constexpr int NQ  = WN / 16;         // ldmatrix x4 groups per warp (4 or 1)
    constexpr int AMB = TMv * 64;        // bytes per A-half stage matrix
    constexpr int BMB = TNv * 64;
    constexpr int STG = 2 * AMB + 2 * BMB;

    extern __shared__ char smem[];
    const uint32_t sb = smem_u32(smem);
    const int tid = threadIdx.x;
    const int wid = tid >> 5, l = tid & 31;
    const int wm = (wid / NWN) * 32;
    const int wn = (wid % NWN) * WN;

    float c[2][NF][4];
#pragma unroll
    for (int i = 0; i < 2; ++i)
#pragma unroll
        for (int j = 0; j < NF; ++j)
#pragma unroll
            for (int q = 0; q < 4; ++q) c[i][j][q] = 0.0f;

    // ldmatrix lane maps (x4)
    const uint32_t a_row = (uint32_t)(wm + (l & 15));                   // + mf*16
    const uint32_t a_ch  = (uint32_t)(l >> 4);                          // + 2*kk
    const uint32_t b_row = (uint32_t)(wn + (l & 7) + ((l & 16) >> 1));  // + q*16
    const uint32_t b_ch  = (uint32_t)((l >> 3) & 1);                    // + 2*kk

    auto issue = [&](int s) {
        const uint32_t bufb = sb + (uint32_t)(s % NBUF) * STG;
        const int ko = s * KC;
#pragma unroll
        for (int i = tid; i < TMv * 4; i += THREADS) {
            const int row = i >> 2, ch = i & 3;
            const uint32_t d = bufb + swz64((uint32_t)(row * 64 + ch * 16));
            const size_t g = (size_t)(m0 + row) * DD_ + ko + ch * 8;
            CP16(d,       Ah + g);
            CP16(d + AMB, Al + g);
        }
#pragma unroll
        for (int i = tid; i < TNv * 4; i += THREADS) {
            const int row = i >> 2, ch = i & 3;
            const uint32_t d = bufb + 2 * AMB + swz64((uint32_t)(row * 64 + ch * 16));
            const size_t g = (size_t)(n0 + row) * DD_ + ko + ch * 8;
            CP16(d,       Bh + g);
            CP16(d + BMB, Bl + g);
        }
    };

    issue(0); CPCOMMIT();
    issue(1); CPCOMMIT();

    for (int s = 0; s < NSTG; ++s) {
        CPWAIT1();
        __syncthreads();

        const uint32_t base = sb + (uint32_t)(s % NBUF) * STG;
        const uint32_t sA  = base;
        const uint32_t sAl = base + AMB;
        const uint32_t sB  = base + 2 * AMB;
        const uint32_t sBl = base + 2 * AMB + BMB;

#pragma unroll
        for (int kk = 0; kk < 2; ++kk) {
            uint32_t ah[2][4], al[2][4], bh[NQ][4], bl[NQ][4];
            const uint32_t ach = (uint32_t)(2 * kk) + a_ch;
            const uint32_t bch = (uint32_t)(2 * kk) + b_ch;
#pragma unroll
            for (int mf = 0; mf < 2; ++mf) {
                const uint32_t off = swz64((a_row + mf * 16) * 64 + ach * 16);
                LDSM4(ah[mf][0], ah[mf][1], ah[mf][2], ah[mf][3], sA + off);
                LDSM4(al[mf][0], al[mf][1], al[mf][2], al[mf][3], sAl + off);
            }
#pragma unroll
            for (int q = 0; q < NQ; ++q) {
                const uint32_t off = swz64((b_row + q * 16) * 64 + bch * 16);
                LDSM4(bh[q][0], bh[q][1], bh[q][2], bh[q][3], sB + off);
                LDSM4(bl[q][0], bl[q][1], bl[q][2], bl[q][3], sBl + off);
            }
#pragma unroll
            for (int mf = 0; mf < 2; ++mf)
#pragma unroll
                for (int nf = 0; nf < NF; ++nf) {
                    const int q = nf >> 1, hh = (nf & 1) * 2;
                    MMA16816(c[mf][nf], ah[mf], bh[q][hh], bh[q][hh + 1]);
                    MMA16816(c[mf][nf], ah[mf], bl[q][hh], bl[q][hh + 1]);
                    MMA16816(c[mf][nf], al[mf], bh[q][hh], bh[q][hh + 1]);
                }
        }
        if (s + 2 < NSTG) issue(s + 2);
        CPCOMMIT();
    }

    // ---------------- epilogue ----------------
    const int row0 = m0 + wm + (l >> 2);
    const int col0 = n0 + wn + 2 * (l & 3);
#pragma unroll
    for (int mf = 0; mf < 2; ++mf)
#pragma unroll
        for (int nf = 0; nf < NF; ++nf) {
            const int rr = row0 + mf * 16;
            const int cc = col0 + nf * 8;
            const float v0 = c[mf][nf][0], v1 = c[mf][nf][1];
            const float v2 = c[mf][nf][2], v3 = c[mf][nf][3];
            if (C) {
                *(float2*)(C + (size_t)rr * cs + cc)       = make_float2(v0, v1);
                *(float2*)(C + (size_t)(rr + 8) * cs + cc) = make_float2(v2, v3);
            }
            if (Ch) {
                uint32_t p01 = bf16x2_pack(v0, v1);
                uint32_t p23 = bf16x2_pack(v2, v3);
                uint32_t q01 = bf16x2_pack(v0 - bf16_lo_f(p01), v1 - bf16_hi_f(p01));
                uint32_t q23 = bf16x2_pack(v2 - bf16_lo_f(p23), v3 - bf16_hi_f(p23));
                *(uint32_t*)(Ch + (size_t)rr * DD_ + cc)       = p01;
                *(uint32_t*)(Cl + (size_t)rr * DD_ + cc)       = q01;
                *(uint32_t*)(Ch + (size_t)(rr + 8) * DD_ + cc) = p23;
                *(uint32_t*)(Cl + (size_t)(rr + 8) * DD_ + cc) = q23;
                if (CTh) {
                    CTh[(size_t)cc * DD_ + rr]           = (uint16_t)p01;
                    CTh[(size_t)(cc + 1) * DD_ + rr]     = (uint16_t)(p01 >> 16);
                    CTh[(size_t)cc * DD_ + rr + 8]       = (uint16_t)p23;
                    CTh[(size_t)(cc + 1) * DD_ + rr + 8] = (uint16_t)(p23 >> 16);
                    CTl[(size_t)cc * DD_ + rr]           = (uint16_t)q01;
                    CTl[(size_t)(cc + 1) * DD_ + rr]     = (uint16_t)(q01 >> 16);
                    CTl[(size_t)cc * DD_ + rr + 8]       = (uint16_t)q23;
                    CTl[(size_t)(cc + 1) * DD_ + rr + 8] = (uint16_t)(q23 >> 16);
                }
            }
        }
}

// ---------------- kernels ----------------

// seed: split K -> slot1 (row-major + transposed), z0 -> anchor 0
__global__ void __launch_bounds__(512) k_seed(const float* __restrict__ K,
                                              const float* __restrict__ z0) {
    int i = blockIdx.x * blockDim.x + threadIdx.x;
    if (i < NDD) {
        float v = K[i];
        uint32_t p = bf16x2_pack(v, v);
        uint16_t hp = (uint16_t)p;
        uint16_t lp = (uint16_t)bf16x2_pack(v - bf16_lo_f(p), 0.0f);
        int r = i >> 9, cc = i & 511;
        gPh[i] = hp;  gPl[i] = lp;
        gPTh[(size_t)cc * DD_ + r] = hp;
        gPTl[(size_t)cc * DD_ + r] = lp;
    } else {
        int j = i - NDD;
        float v = z0[j];
        uint32_t p = bf16x2_pack(v, v);
        gAh[j] = (uint16_t)p;
        gAl[j] = (uint16_t)bf16x2_pack(v - bf16_lo_f(p), 0.0f);
    }
}

// small sequential rounds use 64x64 tiles (short critical path, more CTAs)
#define TS 64

// powers doubling: for z in [0,base): P_{base+z+1} = P_base @ P_{z+1}
__global__ void __launch_bounds__(THREADS, 2) k_power(int base) {
    int z = blockIdx.z;
    int dst = base + z + 1;
    gemmt<TS, TS>(Ph(base), Pl(base), PTh(z + 1), PTl(z + 1),
                  nullptr, 0, Ph(dst), Pl(dst), PTh(dst), PTl(dst),
                  blockIdx.y * TS, blockIdx.x * TS);
}

// round7: z0: K^64 = K^32 @ K^32 (slot 33);  z1: a1 = a0 @ K^32
__global__ void __launch_bounds__(THREADS, 2) k_round7() {
    int m0 = blockIdx.y * TS, n0 = blockIdx.x * TS;
    if (blockIdx.z == 0) {
        gemmt<TS, TS>(Ph(32), Pl(32), PTh(32), PTl(32),
                      nullptr, 0, Ph(33), Pl(33), PTh(33), PTl(33), m0, n0);
    } else {
        if (m0 >= BB) return;
        gemmt<TS, TS>(gAh, gAl, PTh(32), PTl(32),
                      nullptr, 0, gAh + NBD, gAl + NBD, nullptr, nullptr, m0, n0);
    }
}

// round8: z0: K^128 = K^64 @ K^64 (slot 34); z1: a2 = a0 @ K^64; z2: a3 = a1 @ K^64
__global__ void __launch_bounds__(THREADS, 2) k_round8() {
    int m0 = blockIdx.y * TS, n0 = blockIdx.x * TS;
    if (blockIdx.z == 0) {
        gemmt<TS, TS>(Ph(33), Pl(33), PTh(33), PTl(33),
                      nullptr, 0, Ph(34), Pl(34), PTh(34), PTl(34), m0, n0);
    } else {
        if (m0 >= BB) return;
        int i = blockIdx.z - 1;  // 0 or 1
        gemmt<TS, TS>(gAh + (size_t)i * NBD, gAl + (size_t)i * NBD, PTh(33), PTl(33),
                      nullptr, 0, gAh + (size_t)(i + 2) * NBD, gAl + (size_t)(i + 2) * NBD,
                      nullptr, nullptr, m0, n0);
    }
}

// round9: a_{4+z} = a_z @ K^128, z = 0..3
__global__ void __launch_bounds__(THREADS, 2) k_round9() {
    int z = blockIdx.z;
    gemmt<TS, TS>(gAh + (size_t)z * NBD, gAl + (size_t)z * NBD, PTh(34), PTl(34),
                  nullptr, 0, gAh + (size_t)(z + 4) * NBD, gAl + (size_t)(z + 4) * NBD,
                  nullptr, nullptr, blockIdx.y * TS, blockIdx.x * TS);
}

// fine: out[:, t, :] = a_{t>>5} @ K^{(t&31)+1}, all 256 t in parallel (128x128 tiles)
__global__ void __launch_bounds__(THREADS, 2) k_fine(float* __restrict__ out) {
    int t = blockIdx.z;
    gemmt<128, 128>(gAh + (size_t)(t >> 5) * NBD, gAl + (size_t)(t >> 5) * NBD,
                    PTh((t & 31) + 1), PTl((t & 31) + 1),
                    out + (size_t)t * DD_, (size_t)TT * DD_,
                    nullptr, nullptr, nullptr, nullptr,
                    blockIdx.y * 128, blockIdx.x * 128);
}

// ---------------- launch ----------------
extern "C" void kernel_launch(void* const* d_in, const int* in_sizes, int n_in,
                              void* d_out, int out_size) {
    const float* z0 = (const float*)d_in[0];
    const float* K  = (const float*)d_in[1];
    float* out = (float*)d_out;

    cudaFuncSetAttribute(k_power,  cudaFuncAttributeMaxDynamicSharedMemorySize, SMEM_SMALL);
    cudaFuncSetAttribute(k_round7, cudaFuncAttributeMaxDynamicSharedMemorySize, SMEM_SMALL);
    cudaFuncSetAttribute(k_round8, cudaFuncAttributeMaxDynamicSharedMemorySize, SMEM_SMALL);
    cudaFuncSetAttribute(k_round9, cudaFuncAttributeMaxDynamicSharedMemorySize, SMEM_SMALL);
    cudaFuncSetAttribute(k_fine,   cudaFuncAttributeMaxDynamicSharedMemorySize, SMEM_BIG);

    k_seed<<<(NDD + NBD) / 512, 512>>>(K, z0);

    for (int base = 1; base <= 16; base *= 2)
        k_power<<<dim3(DD_ / TS, DD_ / TS, base), THREADS, SMEM_SMALL>>>(base);

    k_round7<<<dim3(DD_ / TS, DD_ / TS, 2), THREADS, SMEM_SMALL>>>();
    k_round8<<<dim3(DD_ / TS, DD_ / TS, 3), THREADS, SMEM_SMALL>>>();
    k_round9<<<dim3(DD_ / TS, BB / TS, 4), THREADS, SMEM_SMALL>>>();

    k_fine<<<dim3(DD_ / 128, BB / 128, TT), THREADS, SMEM_BIG>>>(out);
}